// round 5
// baseline (speedup 1.0000x reference)
#include <cuda_runtime.h>
#include <cuda_bf16.h>
#include <cstdint>

typedef unsigned long long u64;
typedef unsigned int u32;

#define NB 16
#define NT 96
#define NN 325
#define ND 64
#define NH 64
#define NROWS (NB*NN)          // 5200
#define BTN (NB*NT*NN)         // 499200
#define HSTRIDE (NN*NH)        // 20800
#define BSTRIDE (NT*NN*NH)     // 1996800

// Scratch: precomputed input projections, [t][row][cols], row = b*NN+n
__device__ float g_A[(size_t)BTN * 256];   // x@U_x + b_x
__device__ float g_G[(size_t)BTN * 128];   // o_s@U_g + b_g

// ================= helpers =================
__device__ __forceinline__ u32 smem_u32(const void* p){
    u32 a; asm("{ .reg .u64 t; cvta.to.shared.u64 t, %1; cvt.u32.u64 %0, t; }" : "=r"(a) : "l"(p));
    return a;
}
__device__ __forceinline__ u32 bfpack(float lo_elem, float hi_elem){
    u32 r; asm("cvt.rn.bf16x2.f32 %0, %1, %2;" : "=r"(r) : "f"(hi_elem), "f"(lo_elem));
    return r;
}
__device__ __forceinline__ void ldsm_x4(u32& a0,u32& a1,u32& a2,u32& a3, u32 addr){
    asm volatile("ldmatrix.sync.aligned.m8n8.x4.shared.b16 {%0,%1,%2,%3}, [%4];"
      : "=r"(a0),"=r"(a1),"=r"(a2),"=r"(a3) : "r"(addr));
}
__device__ __forceinline__ void ldsm_x2(u32& b0,u32& b1, u32 addr){
    asm volatile("ldmatrix.sync.aligned.m8n8.x2.shared.b16 {%0,%1}, [%2];"
      : "=r"(b0),"=r"(b1) : "r"(addr));
}
__device__ __forceinline__ void mma16816(float* c, const u32* a, const u32* b){
    asm volatile("mma.sync.aligned.m16n8k16.row.col.f32.bf16.bf16.f32 "
      "{%0,%1,%2,%3}, {%4,%5,%6,%7}, {%8,%9}, {%0,%1,%2,%3};"
      : "+f"(c[0]),"+f"(c[1]),"+f"(c[2]),"+f"(c[3])
      : "r"(a[0]),"r"(a[1]),"r"(a[2]),"r"(a[3]), "r"(b[0]),"r"(b[1]));
}

// ---------- packed fp32x2 (phase 2) ----------
__device__ __forceinline__ u64 pack2(float v){
    u64 d; unsigned int b = __float_as_uint(v);
    asm("mov.b64 %0, {%1, %1};" : "=l"(d) : "r"(b));
    return d;
}
__device__ __forceinline__ u64 ffma2(u64 a, u64 b, u64 c){
    u64 d; asm("fma.rn.f32x2 %0, %1, %2, %3;" : "=l"(d) : "l"(a), "l"(b), "l"(c));
    return d;
}
__device__ __forceinline__ float lo32(u64 v){ return __uint_as_float((unsigned)v); }
__device__ __forceinline__ float hi32(u64 v){ return __uint_as_float((unsigned)(v >> 32)); }

// =====================================================================
// Phase 1 (HMMA): per 64-row tile compute fused [xUx+bx | oUg+bg] (N=384)
// via split-3 bf16: A'=[hi|hi|lo] (K'=192), B'=[Whi;Wlo;Whi].  (proven R4)
// =====================================================================
#define P1_THREADS 256
#define P1_ROWS 64
#define P1_TILES (BTN/P1_ROWS)   // 7800
#define P1_GRID 148

#define PITCH 400
#define S_BIAS 0
#define S_B    1536
#define S_AX   155136
#define S_AO   180736
#define P1_SMEM 206336

__global__ void __launch_bounds__(P1_THREADS, 1)
glstm_pre_mma(const float* __restrict__ x, const float* __restrict__ osrc,
              const float* __restrict__ Ux, const float* __restrict__ bx,
              const float* __restrict__ Ug, const float* __restrict__ bg)
{
    extern __shared__ unsigned char smem[];
    float* bias_s = (float*)(smem + S_BIAS);
    const int tid = threadIdx.x;
    const int w   = tid >> 5;
    const int lane = tid & 31;
    const int gid = lane >> 2, tid4 = lane & 3;

    bias_s[tid] = bx[tid];
    if (tid < 128) bias_s[256 + tid] = bg[tid];

    for (int i = tid; i < 64*256; i += P1_THREADS){
        int n = i & 255, k = i >> 8;
        float v = Ux[k*256 + n];
        __nv_bfloat16 hb = __float2bfloat16(v);
        float lo = v - __bfloat162float(hb);
        __nv_bfloat16* row = (__nv_bfloat16*)(smem + S_B + n*PITCH);
        row[k] = hb; row[128 + k] = hb;
        row[64 + k] = __float2bfloat16(lo);
    }
    for (int i = tid; i < 64*128; i += P1_THREADS){
        int n = i & 127, k = i >> 7;
        float v = Ug[k*128 + n];
        __nv_bfloat16 hb = __float2bfloat16(v);
        float lo = v - __bfloat162float(hb);
        __nv_bfloat16* row = (__nv_bfloat16*)(smem + S_B + (256 + n)*PITCH);
        row[k] = hb; row[128 + k] = hb;
        row[64 + k] = __float2bfloat16(lo);
    }

    const u32 sb = smem_u32(smem);
    u32 rowAx[4], rowAo[4];
    #pragma unroll
    for (int mi = 0; mi < 4; mi++){
        u32 off = (u32)(16*mi + (lane & 15))*PITCH + ((lane >> 4) << 4);
        rowAx[mi] = sb + S_AX + off;
        rowAo[mi] = sb + S_AO + off;
    }
    u32 rowB[6];
    #pragma unroll
    for (int ni = 0; ni < 6; ni++)
        rowB[ni] = sb + S_B + (u32)(48*w + 8*ni + (lane & 7))*PITCH + (((lane >> 3) & 1) << 4);

    const bool needx = (w <= 5), needo = (w >= 5);

    const int cr = tid >> 2, ck0 = (tid & 3) << 4;
    u32* ax32 = (u32*)(smem + S_AX + cr*PITCH);
    u32* ao32 = (u32*)(smem + S_AO + cr*PITCH);

    for (int tile = blockIdx.x; tile < P1_TILES; tile += gridDim.x){
        const long long m0 = (long long)tile * P1_ROWS;

        {
            const float4* xp = (const float4*)(x    + (size_t)(m0 + cr)*64 + ck0);
            const float4* op = (const float4*)(osrc + (size_t)(m0 + cr)*64 + ck0);
            float4 xv[4], ov[4];
            #pragma unroll
            for (int j = 0; j < 4; j++){ xv[j] = xp[j]; ov[j] = op[j]; }
            #pragma unroll
            for (int j = 0; j < 4; j++){
                #pragma unroll
                for (int h = 0; h < 2; h++){
                    float a = h ? xv[j].z : xv[j].x;
                    float b = h ? xv[j].w : xv[j].y;
                    int k = ck0 + 4*j + 2*h;
                    u32 hp = bfpack(a, b);
                    float ra = a - __uint_as_float(hp << 16);
                    float rb = b - __uint_as_float(hp & 0xFFFF0000u);
                    u32 lp = bfpack(ra, rb);
                    ax32[k>>1] = hp; ax32[32 + (k>>1)] = hp; ax32[64 + (k>>1)] = lp;

                    a = h ? ov[j].z : ov[j].x;
                    b = h ? ov[j].w : ov[j].y;
                    hp = bfpack(a, b);
                    ra = a - __uint_as_float(hp << 16);
                    rb = b - __uint_as_float(hp & 0xFFFF0000u);
                    lp = bfpack(ra, rb);
                    ao32[k>>1] = hp; ao32[32 + (k>>1)] = hp; ao32[64 + (k>>1)] = lp;
                }
            }
        }
        __syncthreads();

        float acc[4][6][4];
        #pragma unroll
        for (int mi = 0; mi < 4; mi++)
            #pragma unroll
            for (int ni = 0; ni < 6; ni++)
                #pragma unroll
                for (int e = 0; e < 4; e++) acc[mi][ni][e] = 0.0f;

        #pragma unroll
        for (int kf = 0; kf < 12; kf++){
            u32 Axf[4][4], Aof[4][4];
            if (needx){
                #pragma unroll
                for (int mi = 0; mi < 4; mi++)
                    ldsm_x4(Axf[mi][0],Axf[mi][1],Axf[mi][2],Axf[mi][3], rowAx[mi] + kf*32);
            }
            if (needo){
                #pragma unroll
                for (int mi = 0; mi < 4; mi++)
                    ldsm_x4(Aof[mi][0],Aof[mi][1],Aof[mi][2],Aof[mi][3], rowAo[mi] + kf*32);
            }
            u32 Bf[6][2];
            #pragma unroll
            for (int ni = 0; ni < 6; ni++)
                ldsm_x2(Bf[ni][0], Bf[ni][1], rowB[ni] + kf*32);

            #pragma unroll
            for (int ni = 0; ni < 6; ni++){
                const bool isx = (48*w + 8*ni) < 256;
                #pragma unroll
                for (int mi = 0; mi < 4; mi++)
                    mma16816(acc[mi][ni], isx ? Axf[mi] : Aof[mi], Bf[ni]);
            }
        }
        __syncthreads();

        #pragma unroll
        for (int mi = 0; mi < 4; mi++){
            #pragma unroll
            for (int half = 0; half < 2; half++){
                int r = 16*mi + gid + 8*half;
                long long m = m0 + r;
                u32 mu = (u32)m;
                u32 qq = mu / NN;
                u32 n  = mu - qq*NN;
                u32 t  = qq % NT, b = qq / NT;
                size_t ro = (size_t)t*NROWS + (size_t)b*NN + n;
                float* pA = g_A + ro*256;
                float* pG = g_G + ro*128;
                #pragma unroll
                for (int ni = 0; ni < 6; ni++){
                    int col = 48*w + 8*ni + 2*tid4;
                    float2 bv = *(const float2*)&bias_s[col];
                    float2 cv;
                    cv.x = acc[mi][ni][half*2 + 0] + bv.x;
                    cv.y = acc[mi][ni][half*2 + 1] + bv.y;
                    if (col < 256) *(float2*)(pA + col) = cv;
                    else           *(float2*)(pG + col - 256) = cv;
                }
            }
        }
    }
}

// =====================================================================
// Phase 2: recurrence. 130 blocks x 40 rows. 4 independent warp-PAIRS
// per block: pair pr = {warp pr, warp pr+4} owns rows [10*pr, 10*pr+10).
// sub=0 warp: gate pair-groups 0..2 (f,i,o); sub=1: 3..5 (u,gf,gu).
// Pair-local named barriers only; smem exchange of odd-warp partials.
// =====================================================================
#define P2_THREADS 256
#define P2_R 40
#define P2_BLOCKS 130
// Wsi 98304 + hbuf 40960 + xch 20480
#define P2_SMEM (64*192*8 + 2*P2_R*64*8 + P2_R*32*16)

__global__ void __launch_bounds__(P2_THREADS, 1)
glstm_rec(const float* __restrict__ Vx, const float* __restrict__ Vg,
          float* __restrict__ hidden, float* __restrict__ htp, float* __restrict__ ctp)
{
    extern __shared__ unsigned char sraw[];
    u64*    Wsi  = (u64*)sraw;                 // [32][192][2] interleaved
    u64*    hbuf = Wsi + 64*192;               // [2][40][64] duplicated pairs
    float4* xch  = (float4*)(hbuf + 2*P2_R*64);// [40][32]

    const int tid  = threadIdx.x;
    const int lane = tid & 31;
    const int warp = tid >> 5;
    const int pr   = warp & 3;          // pair id (also SMSP id)
    const int sub  = warp >> 2;         // 0: f,i,o  1: u,gf,gu
    const int blk  = blockIdx.x;
    const int r0   = pr*10;             // first row of this pair

    const u64* Vxu = (const u64*)Vx;
    const u64* Vgu = (const u64*)Vg;
    for (int i = tid; i < 64*192; i += P2_THREADS){
        int k = i / 192, jp = i - k*192;
        u64 v = (jp < 128) ? Vxu[k*128 + jp] : Vgu[k*64 + (jp - 128)];
        Wsi[(k >> 1)*384 + jp*2 + (k & 1)] = v;
    }
    for (int i = tid; i < 2*P2_R*64; i += P2_THREADS) hbuf[i] = 0ull;

    // even-warp cell state + output bases (rows r0..r0+9, h = 2*lane, 2*lane+1)
    float c0[10], c1[10];
    int gbase[10], fbase[10];
    #pragma unroll
    for (int j = 0; j < 10; j++){
        c0[j] = 0.0f; c1[j] = 0.0f;
        int rho = blk*P2_R + r0 + j;
        int b = rho / NN, n = rho - b*NN;
        gbase[j] = b*BSTRIDE + n*NH + 2*lane;
        fbase[j] = rho*NH + 2*lane;
    }
    __syncthreads();

    for (int t = 0; t < NT; t++){
        u64* hin  = hbuf + (t & 1)*P2_R*64;
        u64* hout = hbuf + ((t + 1) & 1)*P2_R*64;

        // acc init = input-projection pre-activations (this warp's 3 pair-groups)
        u64 acc[10][3];
        #pragma unroll
        for (int j = 0; j < 10; j++){
            size_t rho = (size_t)blk*P2_R + r0 + j;
            size_t base = (size_t)t*NROWS + rho;
            if (sub == 0){
                const u64* Ap = (const u64*)g_A + base*128;
                acc[j][0] = Ap[lane];            // f
                acc[j][1] = Ap[32 + lane];       // i
                acc[j][2] = Ap[64 + lane];       // o
            } else {
                const u64* Ap = (const u64*)g_A + base*128;
                const u64* Gp = (const u64*)g_G + base*64;
                acc[j][0] = Ap[96 + lane];       // u
                acc[j][1] = Gp[lane];            // gf
                acc[j][2] = Gp[32 + lane];       // gu
            }
        }

        // matmul: += h(t-1) @ V[:, pg*64 .. ]
        const int pgofs = sub*96 + lane;   // (sub*3+p)*32 + lane, p stride 32
        #pragma unroll 4
        for (int kp = 0; kp < 32; kp++){
            ulonglong2 w0 = *(const ulonglong2*)&Wsi[kp*384 + (pgofs      )*2];
            ulonglong2 w1 = *(const ulonglong2*)&Wsi[kp*384 + (pgofs + 32 )*2];
            ulonglong2 w2 = *(const ulonglong2*)&Wsi[kp*384 + (pgofs + 64 )*2];
            #pragma unroll
            for (int j = 0; j < 10; j++){
                ulonglong2 hbv = *(const ulonglong2*)&hin[(r0 + j)*64 + 2*kp];
                acc[j][0] = ffma2(hbv.x, w0.x, acc[j][0]);
                acc[j][0] = ffma2(hbv.y, w0.y, acc[j][0]);
                acc[j][1] = ffma2(hbv.x, w1.x, acc[j][1]);
                acc[j][1] = ffma2(hbv.y, w1.y, acc[j][1]);
                acc[j][2] = ffma2(hbv.x, w2.x, acc[j][2]);
                acc[j][2] = ffma2(hbv.y, w2.y, acc[j][2]);
            }
        }

        if (sub == 1){
            // odd warp: gates u, gf, gu -> partials b1=(1+eg), b2=(1+eu)(1+ev)
            #pragma unroll
            for (int j = 0; j < 10; j++){
                float eu0 = __expf(-lo32(acc[j][0]));
                float eg0 = __expf(-lo32(acc[j][1]));
                float ev0 = __expf(-lo32(acc[j][2]));
                float eu1 = __expf(-hi32(acc[j][0]));
                float eg1 = __expf(-hi32(acc[j][1]));
                float ev1 = __expf(-hi32(acc[j][2]));
                float4 o;
                o.x = 1.0f + eg0;
                o.y = (1.0f + eu0)*(1.0f + ev0);
                o.z = 1.0f + eg1;
                o.w = (1.0f + eu1)*(1.0f + ev1);
                xch[(r0 + j)*32 + lane] = o;
            }
        }
        asm volatile("bar.sync %0, 64;" :: "r"(1 + pr) : "memory");

        if (sub == 0){
            // even warp: finish cell update, write h
            #pragma unroll
            for (int j = 0; j < 10; j++){
                float4 xv = xch[(r0 + j)*32 + lane];
                float hn0, hn1;
                {
                    float ef = __expf(-lo32(acc[j][0]));
                    float fgf = __fdividef(1.0f, (1.0f + ef)*xv.x);
                    float ei = __expf(-lo32(acc[j][1]));
                    float iuu = __fdividef(1.0f, (1.0f + ei)*xv.y);
                    float c = fgf*c0[j] + iuu;
                    c0[j] = c;
                    float ot = __fdividef(1.0f, 1.0f + __expf(-lo32(acc[j][2])));
                    float th = 1.0f - __fdividef(2.0f, 1.0f + __expf(2.0f*c));
                    hn0 = ot * th;
                }
                {
                    float ef = __expf(-hi32(acc[j][0]));
                    float fgf = __fdividef(1.0f, (1.0f + ef)*xv.z);
                    float ei = __expf(-hi32(acc[j][1]));
                    float iuu = __fdividef(1.0f, (1.0f + ei)*xv.w);
                    float c = fgf*c1[j] + iuu;
                    c1[j] = c;
                    float ot = __fdividef(1.0f, 1.0f + __expf(-hi32(acc[j][2])));
                    float th = 1.0f - __fdividef(2.0f, 1.0f + __expf(2.0f*c));
                    hn1 = ot * th;
                }
                ulonglong2 hw; hw.x = pack2(hn0); hw.y = pack2(hn1);
                *(ulonglong2*)&hout[(r0 + j)*64 + 2*lane] = hw;

                float2 hv = make_float2(hn0, hn1);
                *(float2*)&hidden[gbase[j] + t*HSTRIDE] = hv;
                if (t == NT-1){
                    *(float2*)&htp[fbase[j]] = hv;
                    *(float2*)&ctp[fbase[j]] = make_float2(c0[j], c1[j]);
                }
            }
        }
        asm volatile("bar.sync %0, 64;" :: "r"(1 + pr) : "memory");
    }
}

extern "C" void kernel_launch(void* const* d_in, const int* in_sizes, int n_in,
                              void* d_out, int out_size)
{
    const float* x   = (const float*)d_in[0];
    const float* o_s = (const float*)d_in[1];
    const float* Ux  = (const float*)d_in[2];
    const float* Vx  = (const float*)d_in[3];
    const float* bx  = (const float*)d_in[4];
    const float* Ug  = (const float*)d_in[5];
    const float* Vg  = (const float*)d_in[6];
    const float* bg  = (const float*)d_in[7];

    float* out    = (float*)d_out;
    float* hidden = out;                               // [B,T,N,H]
    float* htp    = out + (size_t)BTN * NH;            // [B,N,H]
    float* ctp    = htp + (size_t)NROWS * NH;          // [B,N,H]

    cudaFuncSetAttribute(glstm_pre_mma, cudaFuncAttributeMaxDynamicSharedMemorySize, P1_SMEM);
    cudaFuncSetAttribute(glstm_rec,     cudaFuncAttributeMaxDynamicSharedMemorySize, P2_SMEM);

    glstm_pre_mma<<<P1_GRID, P1_THREADS, P1_SMEM>>>(x, o_s, Ux, bx, Ug, bg);
    glstm_rec<<<P2_BLOCKS, P2_THREADS, P2_SMEM>>>(Vx, Vg, hidden, htp, ctp);
}

// round 6
// speedup vs baseline: 1.2207x; 1.2207x over previous
#include <cuda_runtime.h>
#include <cuda_bf16.h>
#include <cstdint>

typedef unsigned long long u64;
typedef unsigned int u32;

#define NB 16
#define NT 96
#define NN 325
#define ND 64
#define NH 64
#define NROWS (NB*NN)          // 5200
#define BTN (NB*NT*NN)         // 499200
#define HSTRIDE (NN*NH)        // 20800
#define BSTRIDE (NT*NN*NH)     // 1996800

// Fused scratch: [t][row][384] with row = b*NN+n; cols: f,i,o,u,gf,gu (64 each)
__device__ float g_AG[(size_t)BTN * 384];

// ================= helpers =================
__device__ __forceinline__ u32 smem_u32(const void* p){
    u32 a; asm("{ .reg .u64 t; cvta.to.shared.u64 t, %1; cvt.u32.u64 %0, t; }" : "=r"(a) : "l"(p));
    return a;
}
__device__ __forceinline__ u32 bfpack(float lo_elem, float hi_elem){
    u32 r; asm("cvt.rn.bf16x2.f32 %0, %1, %2;" : "=r"(r) : "f"(hi_elem), "f"(lo_elem));
    return r;
}
__device__ __forceinline__ void ldsm_x4(u32& a0,u32& a1,u32& a2,u32& a3, u32 addr){
    asm volatile("ldmatrix.sync.aligned.m8n8.x4.shared.b16 {%0,%1,%2,%3}, [%4];"
      : "=r"(a0),"=r"(a1),"=r"(a2),"=r"(a3) : "r"(addr));
}
__device__ __forceinline__ void ldsm_x2(u32& b0,u32& b1, u32 addr){
    asm volatile("ldmatrix.sync.aligned.m8n8.x2.shared.b16 {%0,%1}, [%2];"
      : "=r"(b0),"=r"(b1) : "r"(addr));
}
__device__ __forceinline__ void mma16816(float* c, const u32* a, const u32* b){
    asm volatile("mma.sync.aligned.m16n8k16.row.col.f32.bf16.bf16.f32 "
      "{%0,%1,%2,%3}, {%4,%5,%6,%7}, {%8,%9}, {%0,%1,%2,%3};"
      : "+f"(c[0]),"+f"(c[1]),"+f"(c[2]),"+f"(c[3])
      : "r"(a[0]),"r"(a[1]),"r"(a[2]),"r"(a[3]), "r"(b[0]),"r"(b[1]));
}

// =====================================================================
// Phase 1 (HMMA, proven R4): per 64-row tile compute fused
// [xUx+bx | oUg+bg] (N=384) via split-3 bf16. Output now FUSED g_AG.
// =====================================================================
#define P1_THREADS 256
#define P1_ROWS 64
#define P1_TILES (BTN/P1_ROWS)   // 7800
#define P1_GRID 148

#define PITCH 400
#define S_BIAS 0
#define S_B    1536
#define S_AX   155136
#define S_AO   180736
#define P1_SMEM 206336

__global__ void __launch_bounds__(P1_THREADS, 1)
glstm_pre_mma(const float* __restrict__ x, const float* __restrict__ osrc,
              const float* __restrict__ Ux, const float* __restrict__ bx,
              const float* __restrict__ Ug, const float* __restrict__ bg)
{
    extern __shared__ unsigned char smem[];
    float* bias_s = (float*)(smem + S_BIAS);
    const int tid = threadIdx.x;
    const int w   = tid >> 5;
    const int lane = tid & 31;
    const int gid = lane >> 2, tid4 = lane & 3;

    bias_s[tid] = bx[tid];
    if (tid < 128) bias_s[256 + tid] = bg[tid];

    for (int i = tid; i < 64*256; i += P1_THREADS){
        int n = i & 255, k = i >> 8;
        float v = Ux[k*256 + n];
        __nv_bfloat16 hb = __float2bfloat16(v);
        float lo = v - __bfloat162float(hb);
        __nv_bfloat16* row = (__nv_bfloat16*)(smem + S_B + n*PITCH);
        row[k] = hb; row[128 + k] = hb;
        row[64 + k] = __float2bfloat16(lo);
    }
    for (int i = tid; i < 64*128; i += P1_THREADS){
        int n = i & 127, k = i >> 7;
        float v = Ug[k*128 + n];
        __nv_bfloat16 hb = __float2bfloat16(v);
        float lo = v - __bfloat162float(hb);
        __nv_bfloat16* row = (__nv_bfloat16*)(smem + S_B + (256 + n)*PITCH);
        row[k] = hb; row[128 + k] = hb;
        row[64 + k] = __float2bfloat16(lo);
    }

    const u32 sb = smem_u32(smem);
    u32 rowAx[4], rowAo[4];
    #pragma unroll
    for (int mi = 0; mi < 4; mi++){
        u32 off = (u32)(16*mi + (lane & 15))*PITCH + ((lane >> 4) << 4);
        rowAx[mi] = sb + S_AX + off;
        rowAo[mi] = sb + S_AO + off;
    }
    u32 rowB[6];
    #pragma unroll
    for (int ni = 0; ni < 6; ni++)
        rowB[ni] = sb + S_B + (u32)(48*w + 8*ni + (lane & 7))*PITCH + (((lane >> 3) & 1) << 4);

    const bool needx = (w <= 5), needo = (w >= 5);

    const int cr = tid >> 2, ck0 = (tid & 3) << 4;
    u32* ax32 = (u32*)(smem + S_AX + cr*PITCH);
    u32* ao32 = (u32*)(smem + S_AO + cr*PITCH);

    for (int tile = blockIdx.x; tile < P1_TILES; tile += gridDim.x){
        const long long m0 = (long long)tile * P1_ROWS;

        {
            const float4* xp = (const float4*)(x    + (size_t)(m0 + cr)*64 + ck0);
            const float4* op = (const float4*)(osrc + (size_t)(m0 + cr)*64 + ck0);
            float4 xv[4], ov[4];
            #pragma unroll
            for (int j = 0; j < 4; j++){ xv[j] = xp[j]; ov[j] = op[j]; }
            #pragma unroll
            for (int j = 0; j < 4; j++){
                #pragma unroll
                for (int h = 0; h < 2; h++){
                    float a = h ? xv[j].z : xv[j].x;
                    float b = h ? xv[j].w : xv[j].y;
                    int k = ck0 + 4*j + 2*h;
                    u32 hp = bfpack(a, b);
                    float ra = a - __uint_as_float(hp << 16);
                    float rb = b - __uint_as_float(hp & 0xFFFF0000u);
                    u32 lp = bfpack(ra, rb);
                    ax32[k>>1] = hp; ax32[32 + (k>>1)] = hp; ax32[64 + (k>>1)] = lp;

                    a = h ? ov[j].z : ov[j].x;
                    b = h ? ov[j].w : ov[j].y;
                    hp = bfpack(a, b);
                    ra = a - __uint_as_float(hp << 16);
                    rb = b - __uint_as_float(hp & 0xFFFF0000u);
                    lp = bfpack(ra, rb);
                    ao32[k>>1] = hp; ao32[32 + (k>>1)] = hp; ao32[64 + (k>>1)] = lp;
                }
            }
        }
        __syncthreads();

        float acc[4][6][4];
        #pragma unroll
        for (int mi = 0; mi < 4; mi++)
            #pragma unroll
            for (int ni = 0; ni < 6; ni++)
                #pragma unroll
                for (int e = 0; e < 4; e++) acc[mi][ni][e] = 0.0f;

        #pragma unroll
        for (int kf = 0; kf < 12; kf++){
            u32 Axf[4][4], Aof[4][4];
            if (needx){
                #pragma unroll
                for (int mi = 0; mi < 4; mi++)
                    ldsm_x4(Axf[mi][0],Axf[mi][1],Axf[mi][2],Axf[mi][3], rowAx[mi] + kf*32);
            }
            if (needo){
                #pragma unroll
                for (int mi = 0; mi < 4; mi++)
                    ldsm_x4(Aof[mi][0],Aof[mi][1],Aof[mi][2],Aof[mi][3], rowAo[mi] + kf*32);
            }
            u32 Bf[6][2];
            #pragma unroll
            for (int ni = 0; ni < 6; ni++)
                ldsm_x2(Bf[ni][0], Bf[ni][1], rowB[ni] + kf*32);

            #pragma unroll
            for (int ni = 0; ni < 6; ni++){
                const bool isx = (48*w + 8*ni) < 256;
                #pragma unroll
                for (int mi = 0; mi < 4; mi++)
                    mma16816(acc[mi][ni], isx ? Axf[mi] : Aof[mi], Bf[ni]);
            }
        }
        __syncthreads();

        #pragma unroll
        for (int mi = 0; mi < 4; mi++){
            #pragma unroll
            for (int half = 0; half < 2; half++){
                int r = 16*mi + gid + 8*half;
                long long m = m0 + r;
                u32 mu = (u32)m;
                u32 qq = mu / NN;
                u32 n  = mu - qq*NN;
                u32 t  = qq % NT, b = qq / NT;
                size_t ro = (size_t)t*NROWS + (size_t)b*NN + n;
                float* pAG = g_AG + ro*384;
                #pragma unroll
                for (int ni = 0; ni < 6; ni++){
                    int col = 48*w + 8*ni + 2*tid4;
                    float2 bv = *(const float2*)&bias_s[col];
                    float2 cv;
                    cv.x = acc[mi][ni][half*2 + 0] + bv.x;
                    cv.y = acc[mi][ni][half*2 + 1] + bv.y;
                    *(float2*)(pAG + col) = cv;
                }
            }
        }
    }
}

// =====================================================================
// Phase 2 (HMMA recurrence): 130 blocks x 40 rows (pad to 48).
// Per step: acc init = g_AG pre-activations (LDG.64 into frags),
// acc += h(t-1)@[Vx|Vg] via split-3 bf16 mma (h,W stored [hi|lo], hi
// frags reused for 3rd pass), acc -> gates smem, elementwise -> h smem.
// =====================================================================
#define P2_THREADS 256
#define P2_R 40
#define P2_BLOCKS 130
#define HPITCH 272                  // bytes per h/B row (128 bf16 + pad)
#define GP 388                      // gates pitch (f32 words)
#define SB_B 0                      // 384*272 = 104448
#define SB_H 104448                 // 48*272  = 13056
#define SB_G 117504                 // 40*388*4 = 62080
#define P2_SMEM (117504 + 40*GP*4)  // 179584

__global__ void __launch_bounds__(P2_THREADS, 1)
glstm_rec_mma(const float* __restrict__ Vx, const float* __restrict__ Vg,
              float* __restrict__ hidden, float* __restrict__ htp, float* __restrict__ ctp)
{
    extern __shared__ unsigned char smem[];
    const u32 sb = smem_u32(smem);
    float* gates = (float*)(smem + SB_G);

    const int tid  = threadIdx.x;
    const int lane = tid & 31;
    const int w    = tid >> 5;      // 0..7
    const int gid  = lane >> 2, tid4 = lane & 3;
    const int blk  = blockIdx.x;

    // ---- build fused B = [Vx | Vg] as [n][hi(64)|lo(64)] bf16, pitch 272 ----
    for (int i = tid; i < 64*384; i += P2_THREADS){
        int k = i / 384, n = i - k*384;
        float v = (n < 256) ? Vx[k*256 + n] : Vg[k*128 + (n - 256)];
        __nv_bfloat16 hb = __float2bfloat16(v);
        __nv_bfloat16* row = (__nv_bfloat16*)(smem + SB_B + n*HPITCH);
        row[k]      = hb;
        row[64 + k] = __float2bfloat16(v - __bfloat162float(hb));
    }
    // ---- zero h (rows 0..47 incl. pad) ----
    for (int i = tid; i < 48*HPITCH/4; i += P2_THREADS)
        ((u32*)(smem + SB_H))[i] = 0;

    // ldmatrix addresses
    u32 rowA[3];
    #pragma unroll
    for (int mi = 0; mi < 3; mi++)
        rowA[mi] = sb + SB_H + (u32)(16*mi + (lane & 15))*HPITCH + ((lane >> 4) << 4);
    u32 rowB[6];
    #pragma unroll
    for (int ni = 0; ni < 6; ni++)
        rowB[ni] = sb + SB_B + (u32)(48*w + 8*ni + (lane & 7))*HPITCH + (((lane >> 3) & 1) << 4);

    // elementwise state: 5 element-pairs per thread (e2 = tid + 256j)
    float c0[5], c1[5];
    int gbase[5], fbase[5];
    #pragma unroll
    for (int j = 0; j < 5; j++){
        c0[j] = 0.0f; c1[j] = 0.0f;
        int e2 = tid + j*P2_THREADS;        // < 1280
        int r = e2 >> 5, hp = e2 & 31;
        int rho = blk*P2_R + r;             // < 5200
        int b = rho / NN, n = rho - b*NN;
        gbase[j] = b*BSTRIDE + n*NH + 2*hp;
        fbase[j] = rho*NH + 2*hp;
    }
    __syncthreads();

    for (int t = 0; t < NT; t++){
        // ---- acc init from fused pre-activations ----
        const float* bt = g_AG + ((size_t)t*NROWS + (size_t)blk*P2_R)*384;
        float acc[3][6][4];
        #pragma unroll
        for (int mi = 0; mi < 3; mi++){
            #pragma unroll
            for (int ni = 0; ni < 6; ni++){
                int col = 48*w + 8*ni + 2*tid4;
                int r0 = 16*mi + gid;
                float2 a0 = *(const float2*)(bt + (size_t)r0*384 + col);
                acc[mi][ni][0] = a0.x; acc[mi][ni][1] = a0.y;
                if (mi < 2){
                    float2 a1 = *(const float2*)(bt + (size_t)(r0 + 8)*384 + col);
                    acc[mi][ni][2] = a1.x; acc[mi][ni][3] = a1.y;
                } else {
                    acc[mi][ni][2] = 0.0f; acc[mi][ni][3] = 0.0f;
                }
            }
        }

        // ---- pass 1: h_hi x W_hi (keep A-hi frags) ----
        u32 Ah[4][3][4];
        #pragma unroll
        for (int kf = 0; kf < 4; kf++){
            #pragma unroll
            for (int mi = 0; mi < 3; mi++)
                ldsm_x4(Ah[kf][mi][0],Ah[kf][mi][1],Ah[kf][mi][2],Ah[kf][mi][3],
                        rowA[mi] + kf*32);
            u32 Bf[6][2];
            #pragma unroll
            for (int ni = 0; ni < 6; ni++)
                ldsm_x2(Bf[ni][0], Bf[ni][1], rowB[ni] + kf*32);
            #pragma unroll
            for (int ni = 0; ni < 6; ni++)
                #pragma unroll
                for (int mi = 0; mi < 3; mi++)
                    mma16816(acc[mi][ni], Ah[kf][mi], Bf[ni]);
        }
        // ---- pass 2: h_hi x W_lo (reuse A-hi) ----
        #pragma unroll
        for (int kf = 0; kf < 4; kf++){
            u32 Bf[6][2];
            #pragma unroll
            for (int ni = 0; ni < 6; ni++)
                ldsm_x2(Bf[ni][0], Bf[ni][1], rowB[ni] + 128 + kf*32);
            #pragma unroll
            for (int ni = 0; ni < 6; ni++)
                #pragma unroll
                for (int mi = 0; mi < 3; mi++)
                    mma16816(acc[mi][ni], Ah[kf][mi], Bf[ni]);
        }
        // ---- pass 3: h_lo x W_hi ----
        #pragma unroll
        for (int kf = 0; kf < 4; kf++){
            u32 Al[3][4];
            #pragma unroll
            for (int mi = 0; mi < 3; mi++)
                ldsm_x4(Al[mi][0],Al[mi][1],Al[mi][2],Al[mi][3],
                        rowA[mi] + 128 + kf*32);
            u32 Bf[6][2];
            #pragma unroll
            for (int ni = 0; ni < 6; ni++)
                ldsm_x2(Bf[ni][0], Bf[ni][1], rowB[ni] + kf*32);
            #pragma unroll
            for (int ni = 0; ni < 6; ni++)
                #pragma unroll
                for (int mi = 0; mi < 3; mi++)
                    mma16816(acc[mi][ni], Al[mi], Bf[ni]);
        }

        // ---- store gates (skip pad rows 40..47) ----
        #pragma unroll
        for (int mi = 0; mi < 3; mi++){
            #pragma unroll
            for (int half = 0; half < 2; half++){
                if (mi == 2 && half == 1) continue;
                int r = 16*mi + gid + 8*half;
                #pragma unroll
                for (int ni = 0; ni < 6; ni++){
                    int col = 48*w + 8*ni + 2*tid4;
                    float2 cv = make_float2(acc[mi][ni][half*2], acc[mi][ni][half*2 + 1]);
                    *(float2*)(gates + (size_t)r*GP + col) = cv;
                }
            }
        }
        __syncthreads();   // gates visible; all h reads done

        // ---- elementwise: sigmoid/tanh cell update, write h (bf16 hi/lo) ----
        #pragma unroll
        for (int j = 0; j < 5; j++){
            int e2 = tid + j*P2_THREADS;
            int r = e2 >> 5, hp = e2 & 31;
            const float* g = gates + (size_t)r*GP + 2*hp;
            float2 gf_ = *(const float2*)(g + 0);
            float2 gi_ = *(const float2*)(g + 64);
            float2 go_ = *(const float2*)(g + 128);
            float2 gu_ = *(const float2*)(g + 192);
            float2 gG_ = *(const float2*)(g + 256);
            float2 gV_ = *(const float2*)(g + 320);

            float hn0, hn1;
            {
                float ef = __expf(-gf_.x);
                float eg = __expf(-gG_.x);
                float fgf = __fdividef(1.0f, 1.0f + ef + eg + ef*eg);
                float ei = __expf(-gi_.x);
                float eu = __expf(-gu_.x);
                float ev = __expf(-gV_.x);
                float iuu = __fdividef(1.0f, (1.0f+ei)*(1.0f+eu)*(1.0f+ev));
                float c = fgf*c0[j] + iuu;
                c0[j] = c;
                float ot = __fdividef(1.0f, 1.0f + __expf(-go_.x));
                float th = 1.0f - __fdividef(2.0f, 1.0f + __expf(2.0f*c));
                hn0 = ot * th;
            }
            {
                float ef = __expf(-gf_.y);
                float eg = __expf(-gG_.y);
                float fgf = __fdividef(1.0f, 1.0f + ef + eg + ef*eg);
                float ei = __expf(-gi_.y);
                float eu = __expf(-gu_.y);
                float ev = __expf(-gV_.y);
                float iuu = __fdividef(1.0f, (1.0f+ei)*(1.0f+eu)*(1.0f+ev));
                float c = fgf*c1[j] + iuu;
                c1[j] = c;
                float ot = __fdividef(1.0f, 1.0f + __expf(-go_.y));
                float th = 1.0f - __fdividef(2.0f, 1.0f + __expf(2.0f*c));
                hn1 = ot * th;
            }

            u32 hhi = bfpack(hn0, hn1);
            float r0 = hn0 - __uint_as_float(hhi << 16);
            float r1 = hn1 - __uint_as_float(hhi & 0xFFFF0000u);
            u32 hlo = bfpack(r0, r1);
            *(u32*)(smem + SB_H + r*HPITCH + 4*hp)       = hhi;
            *(u32*)(smem + SB_H + r*HPITCH + 128 + 4*hp) = hlo;

            float2 hv = make_float2(hn0, hn1);
            *(float2*)&hidden[gbase[j] + t*HSTRIDE] = hv;
            if (t == NT-1){
                *(float2*)&htp[fbase[j]] = hv;
                *(float2*)&ctp[fbase[j]] = make_float2(c0[j], c1[j]);
            }
        }
        __syncthreads();   // h(t) ready for step t+1 ldmatrix
    }
}

extern "C" void kernel_launch(void* const* d_in, const int* in_sizes, int n_in,
                              void* d_out, int out_size)
{
    const float* x   = (const float*)d_in[0];
    const float* o_s = (const float*)d_in[1];
    const float* Ux  = (const float*)d_in[2];
    const float* Vx  = (const float*)d_in[3];
    const float* bx  = (const float*)d_in[4];
    const float* Ug  = (const float*)d_in[5];
    const float* Vg  = (const float*)d_in[6];
    const float* bg  = (const float*)d_in[7];

    float* out    = (float*)d_out;
    float* hidden = out;                               // [B,T,N,H]
    float* htp    = out + (size_t)BTN * NH;            // [B,N,H]
    float* ctp    = htp + (size_t)NROWS * NH;          // [B,N,H]

    cudaFuncSetAttribute(glstm_pre_mma, cudaFuncAttributeMaxDynamicSharedMemorySize, P1_SMEM);
    cudaFuncSetAttribute(glstm_rec_mma, cudaFuncAttributeMaxDynamicSharedMemorySize, P2_SMEM);

    glstm_pre_mma<<<P1_GRID, P1_THREADS, P1_SMEM>>>(x, o_s, Ux, bx, Ug, bg);
    glstm_rec_mma<<<P2_BLOCKS, P2_THREADS, P2_SMEM>>>(Vx, Vg, hidden, htp, ctp);
}

// round 7
// speedup vs baseline: 1.4344x; 1.1751x over previous
#include <cuda_runtime.h>
#include <cuda_bf16.h>
#include <cstdint>

typedef unsigned long long u64;
typedef unsigned int u32;

#define NB 16
#define NT 96
#define NN 325
#define ND 64
#define NH 64
#define NROWS (NB*NN)          // 5200
#define BTN (NB*NT*NN)         // 499200
#define HSTRIDE (NN*NH)        // 20800
#define BSTRIDE (NT*NN*NH)     // 1996800

// Fused scratch: [t][row][384] with row = b*NN+n; cols: f,i,o,u,gf,gu (64 each)
__device__ float g_AG[(size_t)BTN * 384];

// ================= helpers =================
__device__ __forceinline__ u32 smem_u32(const void* p){
    u32 a; asm("{ .reg .u64 t; cvta.to.shared.u64 t, %1; cvt.u32.u64 %0, t; }" : "=r"(a) : "l"(p));
    return a;
}
__device__ __forceinline__ u32 bfpack(float lo_elem, float hi_elem){
    u32 r; asm("cvt.rn.bf16x2.f32 %0, %1, %2;" : "=r"(r) : "f"(hi_elem), "f"(lo_elem));
    return r;
}
__device__ __forceinline__ void ldsm_x4(u32& a0,u32& a1,u32& a2,u32& a3, u32 addr){
    asm volatile("ldmatrix.sync.aligned.m8n8.x4.shared.b16 {%0,%1,%2,%3}, [%4];"
      : "=r"(a0),"=r"(a1),"=r"(a2),"=r"(a3) : "r"(addr));
}
__device__ __forceinline__ void ldsm_x2(u32& b0,u32& b1, u32 addr){
    asm volatile("ldmatrix.sync.aligned.m8n8.x2.shared.b16 {%0,%1}, [%2];"
      : "=r"(b0),"=r"(b1) : "r"(addr));
}
__device__ __forceinline__ void mma16816(float* c, const u32* a, const u32* b){
    asm volatile("mma.sync.aligned.m16n8k16.row.col.f32.bf16.bf16.f32 "
      "{%0,%1,%2,%3}, {%4,%5,%6,%7}, {%8,%9}, {%0,%1,%2,%3};"
      : "+f"(c[0]),"+f"(c[1]),"+f"(c[2]),"+f"(c[3])
      : "r"(a[0]),"r"(a[1]),"r"(a[2]),"r"(a[3]), "r"(b[0]),"r"(b[1]));
}

// =====================================================================
// Phase 1 (HMMA, proven R4/R6) + register prefetch pipelining.
// Per 64-row tile: fused [xUx+bx | oUg+bg] (N=384), split-3 bf16.
// =====================================================================
#define P1_THREADS 256
#define P1_ROWS 64
#define P1_TILES (BTN/P1_ROWS)   // 7800
#define P1_GRID 148

#define PITCH 400
#define S_BIAS 0
#define S_B    1536
#define S_AX   155136
#define S_AO   180736
#define P1_SMEM 206336

__global__ void __launch_bounds__(P1_THREADS, 1)
glstm_pre_mma(const float* __restrict__ x, const float* __restrict__ osrc,
              const float* __restrict__ Ux, const float* __restrict__ bx,
              const float* __restrict__ Ug, const float* __restrict__ bg)
{
    extern __shared__ unsigned char smem[];
    float* bias_s = (float*)(smem + S_BIAS);
    const int tid = threadIdx.x;
    const int w   = tid >> 5;
    const int lane = tid & 31;
    const int gid = lane >> 2, tid4 = lane & 3;

    bias_s[tid] = bx[tid];
    if (tid < 128) bias_s[256 + tid] = bg[tid];

    for (int i = tid; i < 64*256; i += P1_THREADS){
        int n = i & 255, k = i >> 8;
        float v = Ux[k*256 + n];
        __nv_bfloat16 hb = __float2bfloat16(v);
        float lo = v - __bfloat162float(hb);
        __nv_bfloat16* row = (__nv_bfloat16*)(smem + S_B + n*PITCH);
        row[k] = hb; row[128 + k] = hb;
        row[64 + k] = __float2bfloat16(lo);
    }
    for (int i = tid; i < 64*128; i += P1_THREADS){
        int n = i & 127, k = i >> 7;
        float v = Ug[k*128 + n];
        __nv_bfloat16 hb = __float2bfloat16(v);
        float lo = v - __bfloat162float(hb);
        __nv_bfloat16* row = (__nv_bfloat16*)(smem + S_B + (256 + n)*PITCH);
        row[k] = hb; row[128 + k] = hb;
        row[64 + k] = __float2bfloat16(lo);
    }

    const u32 sb = smem_u32(smem);
    u32 rowAx[4], rowAo[4];
    #pragma unroll
    for (int mi = 0; mi < 4; mi++){
        u32 off = (u32)(16*mi + (lane & 15))*PITCH + ((lane >> 4) << 4);
        rowAx[mi] = sb + S_AX + off;
        rowAo[mi] = sb + S_AO + off;
    }
    u32 rowB[6];
    #pragma unroll
    for (int ni = 0; ni < 6; ni++)
        rowB[ni] = sb + S_B + (u32)(48*w + 8*ni + (lane & 7))*PITCH + (((lane >> 3) & 1) << 4);

    const bool needx = (w <= 5), needo = (w >= 5);

    const int cr = tid >> 2, ck0 = (tid & 3) << 4;
    u32* ax32 = (u32*)(smem + S_AX + cr*PITCH);
    u32* ao32 = (u32*)(smem + S_AO + cr*PITCH);

    int tile = blockIdx.x;
    float4 xv[4], ov[4];
    {   // initial prefetch
        const float4* xp = (const float4*)(x    + (size_t)((long long)tile*P1_ROWS + cr)*64 + ck0);
        const float4* op = (const float4*)(osrc + (size_t)((long long)tile*P1_ROWS + cr)*64 + ck0);
        #pragma unroll
        for (int j = 0; j < 4; j++){ xv[j] = xp[j]; ov[j] = op[j]; }
    }

    while (tile < P1_TILES){
        const long long m0 = (long long)tile * P1_ROWS;

        // ---- convert prefetched regs -> A' smem ----
        #pragma unroll
        for (int j = 0; j < 4; j++){
            #pragma unroll
            for (int h = 0; h < 2; h++){
                float a = h ? xv[j].z : xv[j].x;
                float b = h ? xv[j].w : xv[j].y;
                int k = ck0 + 4*j + 2*h;
                u32 hp = bfpack(a, b);
                float ra = a - __uint_as_float(hp << 16);
                float rb = b - __uint_as_float(hp & 0xFFFF0000u);
                u32 lp = bfpack(ra, rb);
                ax32[k>>1] = hp; ax32[32 + (k>>1)] = hp; ax32[64 + (k>>1)] = lp;

                a = h ? ov[j].z : ov[j].x;
                b = h ? ov[j].w : ov[j].y;
                hp = bfpack(a, b);
                ra = a - __uint_as_float(hp << 16);
                rb = b - __uint_as_float(hp & 0xFFFF0000u);
                lp = bfpack(ra, rb);
                ao32[k>>1] = hp; ao32[32 + (k>>1)] = hp; ao32[64 + (k>>1)] = lp;
            }
        }
        __syncthreads();

        // ---- prefetch next tile (hidden under MMA + epilogue) ----
        const int nxt = tile + gridDim.x;
        if (nxt < P1_TILES){
            const float4* xp = (const float4*)(x    + (size_t)((long long)nxt*P1_ROWS + cr)*64 + ck0);
            const float4* op = (const float4*)(osrc + (size_t)((long long)nxt*P1_ROWS + cr)*64 + ck0);
            #pragma unroll
            for (int j = 0; j < 4; j++){ xv[j] = xp[j]; ov[j] = op[j]; }
        }

        // ---- MMA: 64 x 48 slice per warp, K'=192 ----
        float acc[4][6][4];
        #pragma unroll
        for (int mi = 0; mi < 4; mi++)
            #pragma unroll
            for (int ni = 0; ni < 6; ni++)
                #pragma unroll
                for (int e = 0; e < 4; e++) acc[mi][ni][e] = 0.0f;

        #pragma unroll
        for (int kf = 0; kf < 12; kf++){
            u32 Axf[4][4], Aof[4][4];
            if (needx){
                #pragma unroll
                for (int mi = 0; mi < 4; mi++)
                    ldsm_x4(Axf[mi][0],Axf[mi][1],Axf[mi][2],Axf[mi][3], rowAx[mi] + kf*32);
            }
            if (needo){
                #pragma unroll
                for (int mi = 0; mi < 4; mi++)
                    ldsm_x4(Aof[mi][0],Aof[mi][1],Aof[mi][2],Aof[mi][3], rowAo[mi] + kf*32);
            }
            u32 Bf[6][2];
            #pragma unroll
            for (int ni = 0; ni < 6; ni++)
                ldsm_x2(Bf[ni][0], Bf[ni][1], rowB[ni] + kf*32);

            #pragma unroll
            for (int ni = 0; ni < 6; ni++){
                const bool isx = (48*w + 8*ni) < 256;
                #pragma unroll
                for (int mi = 0; mi < 4; mi++)
                    mma16816(acc[mi][ni], isx ? Axf[mi] : Aof[mi], Bf[ni]);
            }
        }
        __syncthreads();

        // ---- epilogue: bias + scatter to fused [t][row] scratch ----
        #pragma unroll
        for (int mi = 0; mi < 4; mi++){
            #pragma unroll
            for (int half = 0; half < 2; half++){
                int r = 16*mi + gid + 8*half;
                long long m = m0 + r;
                u32 mu = (u32)m;
                u32 qq = mu / NN;
                u32 n  = mu - qq*NN;
                u32 t  = qq % NT, b = qq / NT;
                size_t ro = (size_t)t*NROWS + (size_t)b*NN + n;
                float* pAG = g_AG + ro*384;
                #pragma unroll
                for (int ni = 0; ni < 6; ni++){
                    int col = 48*w + 8*ni + 2*tid4;
                    float2 bv = *(const float2*)&bias_s[col];
                    float2 cv;
                    cv.x = acc[mi][ni][half*2 + 0] + bv.x;
                    cv.y = acc[mi][ni][half*2 + 1] + bv.y;
                    *(float2*)(pAG + col) = cv;
                }
            }
        }
        tile = nxt;
    }
}

// =====================================================================
// Phase 2 (HMMA recurrence): 130 blocks x 40 rows (pad to 48).
// apre streamed global->gates smem via cp.async (overlapped with MMA);
// acc starts at 0; gate-store = RMW (apre + acc).
// =====================================================================
#define P2_THREADS 256
#define P2_R 40
#define P2_BLOCKS 130
#define HPITCH 272                  // bytes per h/B row (128 bf16 + pad)
#define GP 388                      // gates pitch (f32 words)
#define SB_B 0                      // 384*272 = 104448
#define SB_H 104448                 // 48*272  = 13056
#define SB_G 117504                 // 40*388*4 = 62080
#define P2_SMEM (117504 + 40*GP*4)  // 179584

__global__ void __launch_bounds__(P2_THREADS, 1)
glstm_rec_mma(const float* __restrict__ Vx, const float* __restrict__ Vg,
              float* __restrict__ hidden, float* __restrict__ htp, float* __restrict__ ctp)
{
    extern __shared__ unsigned char smem[];
    const u32 sb = smem_u32(smem);
    float* gates = (float*)(smem + SB_G);

    const int tid  = threadIdx.x;
    const int lane = tid & 31;
    const int w    = tid >> 5;      // 0..7
    const int gid  = lane >> 2, tid4 = lane & 3;
    const int blk  = blockIdx.x;

    // ---- build fused B = [Vx | Vg] as [n][hi(64)|lo(64)] bf16, pitch 272 ----
    for (int i = tid; i < 64*384; i += P2_THREADS){
        int k = i / 384, n = i - k*384;
        float v = (n < 256) ? Vx[k*256 + n] : Vg[k*128 + (n - 256)];
        __nv_bfloat16 hb = __float2bfloat16(v);
        __nv_bfloat16* row = (__nv_bfloat16*)(smem + SB_B + n*HPITCH);
        row[k]      = hb;
        row[64 + k] = __float2bfloat16(v - __bfloat162float(hb));
    }
    // ---- zero h (rows 0..47 incl. pad) ----
    for (int i = tid; i < 48*HPITCH/4; i += P2_THREADS)
        ((u32*)(smem + SB_H))[i] = 0;

    // ldmatrix addresses
    u32 rowA[3];
    #pragma unroll
    for (int mi = 0; mi < 3; mi++)
        rowA[mi] = sb + SB_H + (u32)(16*mi + (lane & 15))*HPITCH + ((lane >> 4) << 4);
    u32 rowB[6];
    #pragma unroll
    for (int ni = 0; ni < 6; ni++)
        rowB[ni] = sb + SB_B + (u32)(48*w + 8*ni + (lane & 7))*HPITCH + (((lane >> 3) & 1) << 4);

    // elementwise state: 5 element-pairs per thread (e2 = tid + 256j)
    float c0[5], c1[5];
    int gbase[5], fbase[5];
    #pragma unroll
    for (int j = 0; j < 5; j++){
        c0[j] = 0.0f; c1[j] = 0.0f;
        int e2 = tid + j*P2_THREADS;        // < 1280
        int r = e2 >> 5, hp = e2 & 31;
        int rho = blk*P2_R + r;             // < 5200
        int b = rho / NN, n = rho - b*NN;
        gbase[j] = b*BSTRIDE + n*NH + 2*hp;
        fbase[j] = rho*NH + 2*hp;
    }
    __syncthreads();

    for (int t = 0; t < NT; t++){
        // ---- 1) stream apre slab into gates smem (async, overlaps MMA) ----
        {
            const float* src = g_AG + ((size_t)t*NROWS + (size_t)blk*P2_R)*384;
            #pragma unroll
            for (int j = 0; j < 15; j++){
                int i = tid + j*P2_THREADS;     // < 3840 chunks of 16B
                int r = i / 96, c = i - r*96;
                u32 dst = sb + SB_G + (u32)r*(GP*4) + (u32)c*16;
                const float* s = src + (size_t)r*384 + (size_t)c*4;
                asm volatile("cp.async.ca.shared.global [%0], [%1], 16;"
                             :: "r"(dst), "l"(s) : "memory");
            }
            asm volatile("cp.async.commit_group;" ::: "memory");
        }

        // ---- 2) MMA, acc = 0 ----
        float acc[3][6][4];
        #pragma unroll
        for (int mi = 0; mi < 3; mi++)
            #pragma unroll
            for (int ni = 0; ni < 6; ni++)
                #pragma unroll
                for (int e = 0; e < 4; e++) acc[mi][ni][e] = 0.0f;

        // pass 1: h_hi x W_hi (keep A-hi frags)
        u32 Ah[4][3][4];
        #pragma unroll
        for (int kf = 0; kf < 4; kf++){
            #pragma unroll
            for (int mi = 0; mi < 3; mi++)
                ldsm_x4(Ah[kf][mi][0],Ah[kf][mi][1],Ah[kf][mi][2],Ah[kf][mi][3],
                        rowA[mi] + kf*32);
            u32 Bf[6][2];
            #pragma unroll
            for (int ni = 0; ni < 6; ni++)
                ldsm_x2(Bf[ni][0], Bf[ni][1], rowB[ni] + kf*32);
            #pragma unroll
            for (int ni = 0; ni < 6; ni++)
                #pragma unroll
                for (int mi = 0; mi < 3; mi++)
                    mma16816(acc[mi][ni], Ah[kf][mi], Bf[ni]);
        }
        // pass 2: h_hi x W_lo (reuse A-hi)
        #pragma unroll
        for (int kf = 0; kf < 4; kf++){
            u32 Bf[6][2];
            #pragma unroll
            for (int ni = 0; ni < 6; ni++)
                ldsm_x2(Bf[ni][0], Bf[ni][1], rowB[ni] + 128 + kf*32);
            #pragma unroll
            for (int ni = 0; ni < 6; ni++)
                #pragma unroll
                for (int mi = 0; mi < 3; mi++)
                    mma16816(acc[mi][ni], Ah[kf][mi], Bf[ni]);
        }
        // pass 3: h_lo x W_hi
        #pragma unroll
        for (int kf = 0; kf < 4; kf++){
            u32 Al[3][4];
            #pragma unroll
            for (int mi = 0; mi < 3; mi++)
                ldsm_x4(Al[mi][0],Al[mi][1],Al[mi][2],Al[mi][3],
                        rowA[mi] + 128 + kf*32);
            u32 Bf[6][2];
            #pragma unroll
            for (int ni = 0; ni < 6; ni++)
                ldsm_x2(Bf[ni][0], Bf[ni][1], rowB[ni] + kf*32);
            #pragma unroll
            for (int ni = 0; ni < 6; ni++)
                #pragma unroll
                for (int mi = 0; mi < 3; mi++)
                    mma16816(acc[mi][ni], Al[mi], Bf[ni]);
        }

        // ---- 3) apre landed; make visible ----
        asm volatile("cp.async.wait_group 0;" ::: "memory");
        __syncthreads();

        // ---- 4) gate-store RMW: gates = apre + acc (skip pad rows) ----
        #pragma unroll
        for (int mi = 0; mi < 3; mi++){
            #pragma unroll
            for (int half = 0; half < 2; half++){
                if (mi == 2 && half == 1) continue;
                int r = 16*mi + gid + 8*half;
                #pragma unroll
                for (int ni = 0; ni < 6; ni++){
                    int col = 48*w + 8*ni + 2*tid4;
                    float* gp = gates + (size_t)r*GP + col;
                    float2 prev = *(const float2*)gp;
                    float2 cv = make_float2(acc[mi][ni][half*2] + prev.x,
                                            acc[mi][ni][half*2 + 1] + prev.y);
                    *(float2*)gp = cv;
                }
            }
        }
        __syncthreads();   // gates complete; all h reads done

        // ---- 5) elementwise: cell update, write h (bf16 hi/lo) ----
        #pragma unroll
        for (int j = 0; j < 5; j++){
            int e2 = tid + j*P2_THREADS;
            int r = e2 >> 5, hp = e2 & 31;
            const float* g = gates + (size_t)r*GP + 2*hp;
            float2 gf_ = *(const float2*)(g + 0);
            float2 gi_ = *(const float2*)(g + 64);
            float2 go_ = *(const float2*)(g + 128);
            float2 gu_ = *(const float2*)(g + 192);
            float2 gG_ = *(const float2*)(g + 256);
            float2 gV_ = *(const float2*)(g + 320);

            float hn0, hn1;
            {
                float ef = __expf(-gf_.x);
                float eg = __expf(-gG_.x);
                float fgf = __fdividef(1.0f, 1.0f + ef + eg + ef*eg);
                float ei = __expf(-gi_.x);
                float eu = __expf(-gu_.x);
                float ev = __expf(-gV_.x);
                float iuu = __fdividef(1.0f, (1.0f+ei)*(1.0f+eu)*(1.0f+ev));
                float c = fgf*c0[j] + iuu;
                c0[j] = c;
                float ot = __fdividef(1.0f, 1.0f + __expf(-go_.x));
                float th = 1.0f - __fdividef(2.0f, 1.0f + __expf(2.0f*c));
                hn0 = ot * th;
            }
            {
                float ef = __expf(-gf_.y);
                float eg = __expf(-gG_.y);
                float fgf = __fdividef(1.0f, 1.0f + ef + eg + ef*eg);
                float ei = __expf(-gi_.y);
                float eu = __expf(-gu_.y);
                float ev = __expf(-gV_.y);
                float iuu = __fdividef(1.0f, (1.0f+ei)*(1.0f+eu)*(1.0f+ev));
                float c = fgf*c1[j] + iuu;
                c1[j] = c;
                float ot = __fdividef(1.0f, 1.0f + __expf(-go_.y));
                float th = 1.0f - __fdividef(2.0f, 1.0f + __expf(2.0f*c));
                hn1 = ot * th;
            }

            u32 hhi = bfpack(hn0, hn1);
            float r0 = hn0 - __uint_as_float(hhi << 16);
            float r1 = hn1 - __uint_as_float(hhi & 0xFFFF0000u);
            u32 hlo = bfpack(r0, r1);
            *(u32*)(smem + SB_H + r*HPITCH + 4*hp)       = hhi;
            *(u32*)(smem + SB_H + r*HPITCH + 128 + 4*hp) = hlo;

            float2 hv = make_float2(hn0, hn1);
            *(float2*)&hidden[gbase[j] + t*HSTRIDE] = hv;
            if (t == NT-1){
                *(float2*)&htp[fbase[j]] = hv;
                *(float2*)&ctp[fbase[j]] = make_float2(c0[j], c1[j]);
            }
        }
        __syncthreads();   // h(t) ready for step t+1 ldmatrix
    }
}

extern "C" void kernel_launch(void* const* d_in, const int* in_sizes, int n_in,
                              void* d_out, int out_size)
{
    const float* x   = (const float*)d_in[0];
    const float* o_s = (const float*)d_in[1];
    const float* Ux  = (const float*)d_in[2];
    const float* Vx  = (const float*)d_in[3];
    const float* bx  = (const float*)d_in[4];
    const float* Ug  = (const float*)d_in[5];
    const float* Vg  = (const float*)d_in[6];
    const float* bg  = (const float*)d_in[7];

    float* out    = (float*)d_out;
    float* hidden = out;                               // [B,T,N,H]
    float* htp    = out + (size_t)BTN * NH;            // [B,N,H]
    float* ctp    = htp + (size_t)NROWS * NH;          // [B,N,H]

    cudaFuncSetAttribute(glstm_pre_mma, cudaFuncAttributeMaxDynamicSharedMemorySize, P1_SMEM);
    cudaFuncSetAttribute(glstm_rec_mma, cudaFuncAttributeMaxDynamicSharedMemorySize, P2_SMEM);

    glstm_pre_mma<<<P1_GRID, P1_THREADS, P1_SMEM>>>(x, o_s, Ux, bx, Ug, bg);
    glstm_rec_mma<<<P2_BLOCKS, P2_THREADS, P2_SMEM>>>(Vx, Vg, hidden, htp, ctp);
}